// round 3
// baseline (speedup 1.0000x reference)
#include <cuda_runtime.h>
#include <cuda_bf16.h>
#include <math.h>

#define N_NODES 50000
#define N_EDGES 800000
#define NH 4
#define FOUT 32
#define FIN 128          // = NH*FOUT
#define LEAKY 0.2f

// ---------------- device scratch (static, allocation-free) ----------------
// __align__(16): accessed as float4 (128-bit LDG/STG and vector atomics).
__device__ __align__(16) float g_proj[N_NODES * FIN];       // 25.6 MB
__device__ __align__(16) float g_s_src[N_NODES * NH];
__device__ __align__(16) float g_s_trg[N_NODES * NH];
__device__ __align__(16) float g_denom[N_NODES * NH];
__device__ float g_max;

// ---------------- helpers ----------------
__device__ __forceinline__ void atomicMaxFloat(float* addr, float value) {
    if (value >= 0.f) atomicMax((int*)addr, __float_as_int(value));
    else              atomicMin((unsigned int*)addr, __float_as_uint(value));
}

// ---------------- kernel 1: init out = x + bias, zero denom, reset max ----
__global__ void k_init(const float* __restrict__ x, const float* __restrict__ bias,
                       float* __restrict__ out, int total) {
    int i = blockIdx.x * blockDim.x + threadIdx.x;
    int stride = gridDim.x * blockDim.x;
    for (; i < total; i += stride) {
        out[i] = x[i] + bias[i & (FIN - 1)];
        if (i < N_NODES * NH) g_denom[i] = 0.f;
    }
    if (blockIdx.x == 0 && threadIdx.x == 0) g_max = __uint_as_float(0xFF800000u); // -inf
}

// ---------------- kernel 2: proj = x@W (+ per-node s_src/s_trg) ----------
#define BM 64
#define BK 32
__global__ __launch_bounds__(256) void k_gemm(const float* __restrict__ x,
                                              const float* __restrict__ W,
                                              const float* __restrict__ a_src,
                                              const float* __restrict__ a_trg) {
    __shared__ __align__(16) float xs[BM][BK];
    __shared__ __align__(16) float ws[BK][FIN];
    const int tid = threadIdx.x;
    const int ty = tid >> 5;      // 0..7
    const int tx = tid & 31;      // 0..31
    const int row0 = blockIdx.x * BM;

    float acc[8][4];
#pragma unroll
    for (int i = 0; i < 8; i++)
#pragma unroll
        for (int j = 0; j < 4; j++) acc[i][j] = 0.f;

    for (int kc = 0; kc < FIN; kc += BK) {
#pragma unroll
        for (int i = 0; i < (BM * BK) / 256; i++) {       // 8 iters
            int idx = tid + i * 256;
            int r = idx >> 5, k = idx & 31;
            int gr = row0 + r;
            xs[r][k] = (gr < N_NODES) ? x[gr * FIN + kc + k] : 0.f;
        }
#pragma unroll
        for (int i = 0; i < (BK * FIN) / 256; i++) {      // 16 iters
            int idx = tid + i * 256;
            int k = idx >> 7, c = idx & 127;
            ws[k][c] = W[(kc + k) * FIN + c];
        }
        __syncthreads();
#pragma unroll
        for (int k = 0; k < BK; k++) {
            float b[4];
            *(float4*)b = *(const float4*)&ws[k][tx * 4];
#pragma unroll
            for (int i = 0; i < 8; i++) {
                float a = xs[ty * 8 + i][k];
                acc[i][0] = fmaf(a, b[0], acc[i][0]);
                acc[i][1] = fmaf(a, b[1], acc[i][1]);
                acc[i][2] = fmaf(a, b[2], acc[i][2]);
                acc[i][3] = fmaf(a, b[3], acc[i][3]);
            }
        }
        __syncthreads();
    }

    // epilogue: write proj + per-head attention score partial reductions
    const int head = tx >> 3;                   // lanes 0-7 -> head0, ...
    float as[4], at[4];
#pragma unroll
    for (int j = 0; j < 4; j++) {
        int c = tx * 4 + j;
        int f = c & (FOUT - 1);
        as[j] = __ldg(&a_src[head * FOUT + f]);
        at[j] = __ldg(&a_trg[head * FOUT + f]);
    }
#pragma unroll
    for (int i = 0; i < 8; i++) {
        int gr = row0 + ty * 8 + i;
        if (gr >= N_NODES) continue;
        *(float4*)&g_proj[gr * FIN + tx * 4] = *(float4*)acc[i];
        float ps = acc[i][0] * as[0] + acc[i][1] * as[1] + acc[i][2] * as[2] + acc[i][3] * as[3];
        float pt = acc[i][0] * at[0] + acc[i][1] * at[1] + acc[i][2] * at[2] + acc[i][3] * at[3];
#pragma unroll
        for (int o = 1; o < 8; o <<= 1) {
            ps += __shfl_xor_sync(0xffffffffu, ps, o);
            pt += __shfl_xor_sync(0xffffffffu, pt, o);
        }
        if ((tx & 7) == 0) {
            g_s_src[gr * NH + head] = ps;
            g_s_trg[gr * NH + head] = pt;
        }
    }
}

// ---------------- kernel 3: global max over leaky edge scores ------------
__global__ void k_edge_max(const int* __restrict__ ei, int E) {
    float m = __uint_as_float(0xFF800000u);
    int i = blockIdx.x * blockDim.x + threadIdx.x;
    int stride = gridDim.x * blockDim.x;
    for (; i < E; i += stride) {
        int src = ei[i];
        int trg = ei[E + i];
        float4 ss = *(const float4*)&g_s_src[src * NH];
        float4 st = *(const float4*)&g_s_trg[trg * NH];
        float v;
        v = ss.x + st.x; v = v > 0.f ? v : LEAKY * v; m = fmaxf(m, v);
        v = ss.y + st.y; v = v > 0.f ? v : LEAKY * v; m = fmaxf(m, v);
        v = ss.z + st.z; v = v > 0.f ? v : LEAKY * v; m = fmaxf(m, v);
        v = ss.w + st.w; v = v > 0.f ? v : LEAKY * v; m = fmaxf(m, v);
    }
#pragma unroll
    for (int o = 16; o >= 1; o >>= 1) m = fmaxf(m, __shfl_xor_sync(0xffffffffu, m, o));
    __shared__ float sm[32];
    int lane = threadIdx.x & 31, warp = threadIdx.x >> 5;
    if (lane == 0) sm[warp] = m;
    __syncthreads();
    if (warp == 0) {
        int nw = (blockDim.x + 31) >> 5;
        m = (lane < nw) ? sm[lane] : __uint_as_float(0xFF800000u);
#pragma unroll
        for (int o = 16; o >= 1; o >>= 1) m = fmaxf(m, __shfl_xor_sync(0xffffffffu, m, o));
        if (lane == 0) atomicMaxFloat(&g_max, m);
    }
}

// ---------------- kernel 4: denom[trg][h] += exp(e - max) ----------------
__global__ void k_denom(const int* __restrict__ ei, int E) {
    int i = blockIdx.x * blockDim.x + threadIdx.x;
    if (i >= E) return;
    float gm = g_max;
    int src = ei[i];
    int trg = ei[E + i];
    float4 ss = *(const float4*)&g_s_src[src * NH];
    float4 st = *(const float4*)&g_s_trg[trg * NH];
    float4 ex;
    float v;
    v = ss.x + st.x; v = v > 0.f ? v : LEAKY * v; ex.x = expf(v - gm);
    v = ss.y + st.y; v = v > 0.f ? v : LEAKY * v; ex.y = expf(v - gm);
    v = ss.z + st.z; v = v > 0.f ? v : LEAKY * v; ex.z = expf(v - gm);
    v = ss.w + st.w; v = v > 0.f ? v : LEAKY * v; ex.w = expf(v - gm);
    atomicAdd((float4*)&g_denom[trg * NH], ex);   // sm_90+ vector atomic
}

// ---------------- kernel 5: out[trg] += proj[src] * att (warp per edge) --
__global__ __launch_bounds__(256) void k_aggregate(const int* __restrict__ ei,
                                                   float* __restrict__ out, int E) {
    int e = (blockIdx.x * blockDim.x + threadIdx.x) >> 5;
    if (e >= E) return;
    const int lane = threadIdx.x & 31;
    const int head = lane >> 3;               // lane's 4 cols are all in this head
    int src = ei[e];                          // broadcast load
    int trg = ei[E + e];
    float gm = g_max;
    float ss = g_s_src[src * NH + head];
    float st = g_s_trg[trg * NH + head];
    float v = ss + st; v = v > 0.f ? v : LEAKY * v;
    float att = expf(v - gm) / (g_denom[trg * NH + head] + 1e-16f);
    float4 p = *(const float4*)&g_proj[src * FIN + lane * 4];
    float4 w;
    w.x = p.x * att; w.y = p.y * att; w.z = p.z * att; w.w = p.w * att;
    atomicAdd((float4*)&out[trg * FIN + lane * 4], w);
}

// ---------------- kernel 6: out = elu(out) -------------------------------
__global__ void k_elu(float* __restrict__ out, int total) {
    int i = blockIdx.x * blockDim.x + threadIdx.x;
    int stride = gridDim.x * blockDim.x;
    for (; i < total; i += stride) {
        float v = out[i];
        out[i] = v > 0.f ? v : expm1f(v);
    }
}

// ---------------- launch -------------------------------------------------
extern "C" void kernel_launch(void* const* d_in, const int* in_sizes, int n_in,
                              void* d_out, int out_size) {
    const float* x     = (const float*)d_in[0];
    const int*   ei    = (const int*)d_in[1];   // JAX x64 disabled: int64 request -> int32
    const float* W     = (const float*)d_in[2];
    const float* a_src = (const float*)d_in[3];
    const float* a_trg = (const float*)d_in[4];
    const float* bias  = (const float*)d_in[5];
    float* out = (float*)d_out;

    const int E = in_sizes[1] / 2;
    const int total = N_NODES * FIN;

    k_init<<<2048, 256>>>(x, bias, out, total);
    k_gemm<<<(N_NODES + BM - 1) / BM, 256>>>(x, W, a_src, a_trg);
    k_edge_max<<<1024, 256>>>(ei, E);
    k_denom<<<(E + 255) / 256, 256>>>(ei, E);
    k_aggregate<<<(E * 32 + 255) / 256, 256>>>(ei, out, E);
    k_elu<<<2048, 256>>>(out, total);
}

// round 4
// speedup vs baseline: 1.3601x; 1.3601x over previous
#include <cuda_runtime.h>
#include <cuda_bf16.h>
#include <math.h>

#define N_NODES 50000
#define N_EDGES 800000
#define NH 4
#define FOUT 32
#define FIN 128          // = NH*FOUT
#define LEAKY 0.2f
#define NB_CHUNKS ((N_NODES + 255) / 256)   // 196

// ---------------- device scratch (static, allocation-free) ----------------
__device__ __align__(16) float g_proj[N_NODES * FIN];       // 25.6 MB
__device__ __align__(16) float g_s_src[N_NODES * NH];
__device__ __align__(16) float g_s_trg[N_NODES * NH];
__device__ float g_max;
// CSR build
__device__ int g_cnt[N_NODES];
__device__ int g_off[N_NODES];
__device__ int g_cur[N_NODES];
__device__ int g_bsum[256];
__device__ int g_esrc[N_EDGES];

// ---------------- helpers ----------------
__device__ __forceinline__ void atomicMaxFloat(float* addr, float value) {
    if (value >= 0.f) atomicMax((int*)addr, __float_as_int(value));
    else              atomicMin((unsigned int*)addr, __float_as_uint(value));
}

// ---------------- kernel: zero counts, reset max -------------------------
__global__ void k_zero() {
    int i = blockIdx.x * blockDim.x + threadIdx.x;
    if (i < N_NODES) g_cnt[i] = 0;
    if (i == 0) g_max = __uint_as_float(0xFF800000u); // -inf
}

// ---------------- kernel: proj = x@W (+ per-node s_src/s_trg) ------------
#define BM 64
#define BK 32
__global__ __launch_bounds__(256) void k_gemm(const float* __restrict__ x,
                                              const float* __restrict__ W,
                                              const float* __restrict__ a_src,
                                              const float* __restrict__ a_trg) {
    __shared__ __align__(16) float xs[BM][BK];
    __shared__ __align__(16) float ws[BK][FIN];
    const int tid = threadIdx.x;
    const int ty = tid >> 5;      // 0..7
    const int tx = tid & 31;      // 0..31
    const int row0 = blockIdx.x * BM;

    float acc[8][4];
#pragma unroll
    for (int i = 0; i < 8; i++)
#pragma unroll
        for (int j = 0; j < 4; j++) acc[i][j] = 0.f;

    for (int kc = 0; kc < FIN; kc += BK) {
#pragma unroll
        for (int i = 0; i < (BM * BK) / 256; i++) {
            int idx = tid + i * 256;
            int r = idx >> 5, k = idx & 31;
            int gr = row0 + r;
            xs[r][k] = (gr < N_NODES) ? x[gr * FIN + kc + k] : 0.f;
        }
#pragma unroll
        for (int i = 0; i < (BK * FIN) / 256; i++) {
            int idx = tid + i * 256;
            int k = idx >> 7, c = idx & 127;
            ws[k][c] = W[(kc + k) * FIN + c];
        }
        __syncthreads();
#pragma unroll
        for (int k = 0; k < BK; k++) {
            float b[4];
            *(float4*)b = *(const float4*)&ws[k][tx * 4];
#pragma unroll
            for (int i = 0; i < 8; i++) {
                float a = xs[ty * 8 + i][k];
                acc[i][0] = fmaf(a, b[0], acc[i][0]);
                acc[i][1] = fmaf(a, b[1], acc[i][1]);
                acc[i][2] = fmaf(a, b[2], acc[i][2]);
                acc[i][3] = fmaf(a, b[3], acc[i][3]);
            }
        }
        __syncthreads();
    }

    const int head = tx >> 3;
    float as[4], at[4];
#pragma unroll
    for (int j = 0; j < 4; j++) {
        int f = (tx * 4 + j) & (FOUT - 1);
        as[j] = __ldg(&a_src[head * FOUT + f]);
        at[j] = __ldg(&a_trg[head * FOUT + f]);
    }
#pragma unroll
    for (int i = 0; i < 8; i++) {
        int gr = row0 + ty * 8 + i;
        if (gr >= N_NODES) continue;
        *(float4*)&g_proj[gr * FIN + tx * 4] = *(float4*)acc[i];
        float ps = acc[i][0] * as[0] + acc[i][1] * as[1] + acc[i][2] * as[2] + acc[i][3] * as[3];
        float pt = acc[i][0] * at[0] + acc[i][1] * at[1] + acc[i][2] * at[2] + acc[i][3] * at[3];
#pragma unroll
        for (int o = 1; o < 8; o <<= 1) {
            ps += __shfl_xor_sync(0xffffffffu, ps, o);
            pt += __shfl_xor_sync(0xffffffffu, pt, o);
        }
        if ((tx & 7) == 0) {
            g_s_src[gr * NH + head] = ps;
            g_s_trg[gr * NH + head] = pt;
        }
    }
}

// ---------------- CSR build: count / scan / scatter ----------------------
__global__ void k_count(const int* __restrict__ ei, int E) {
    int i = blockIdx.x * blockDim.x + threadIdx.x;
    if (i < E) atomicAdd(&g_cnt[ei[E + i]], 1);
}

__global__ void k_scan1() {
    __shared__ int s[256];
    int b = blockIdx.x, t = threadIdx.x, i = b * 256 + t;
    int v = (i < N_NODES) ? g_cnt[i] : 0;
    s[t] = v;
    __syncthreads();
#pragma unroll
    for (int o = 1; o < 256; o <<= 1) {
        int u = (t >= o) ? s[t - o] : 0;
        __syncthreads();
        s[t] += u;
        __syncthreads();
    }
    if (i < N_NODES) g_off[i] = s[t] - v;     // chunk-local exclusive
    if (t == 255) g_bsum[b] = s[255];
}

__global__ void k_scan2(int nb) {
    __shared__ int s[256];
    int t = threadIdx.x;
    int v = (t < nb) ? g_bsum[t] : 0;
    s[t] = v;
    __syncthreads();
#pragma unroll
    for (int o = 1; o < 256; o <<= 1) {
        int u = (t >= o) ? s[t - o] : 0;
        __syncthreads();
        s[t] += u;
        __syncthreads();
    }
    if (t < nb) g_bsum[t] = s[t] - v;         // exclusive block offsets
}

__global__ void k_scan_add() {
    int i = blockIdx.x * blockDim.x + threadIdx.x;
    if (i < N_NODES) {
        int off = g_off[i] + g_bsum[i >> 8];
        g_off[i] = off;
        g_cur[i] = off;
    }
}

__global__ void k_scatter(const int* __restrict__ ei, int E) {
    int i = blockIdx.x * blockDim.x + threadIdx.x;
    if (i >= E) return;
    int src = ei[i];
    int trg = ei[E + i];
    int pos = atomicAdd(&g_cur[trg], 1);
    g_esrc[pos] = src;
}

// ---------------- kernel: global max over leaky edge scores --------------
__global__ void k_edge_max(const int* __restrict__ ei, int E) {
    float m = __uint_as_float(0xFF800000u);
    int i = blockIdx.x * blockDim.x + threadIdx.x;
    int stride = gridDim.x * blockDim.x;
    for (; i < E; i += stride) {
        int src = ei[i];
        int trg = ei[E + i];
        float4 ss = *(const float4*)&g_s_src[src * NH];
        float4 st = *(const float4*)&g_s_trg[trg * NH];
        float v;
        v = ss.x + st.x; v = v > 0.f ? v : LEAKY * v; m = fmaxf(m, v);
        v = ss.y + st.y; v = v > 0.f ? v : LEAKY * v; m = fmaxf(m, v);
        v = ss.z + st.z; v = v > 0.f ? v : LEAKY * v; m = fmaxf(m, v);
        v = ss.w + st.w; v = v > 0.f ? v : LEAKY * v; m = fmaxf(m, v);
    }
#pragma unroll
    for (int o = 16; o >= 1; o >>= 1) m = fmaxf(m, __shfl_xor_sync(0xffffffffu, m, o));
    __shared__ float sm[32];
    int lane = threadIdx.x & 31, warp = threadIdx.x >> 5;
    if (lane == 0) sm[warp] = m;
    __syncthreads();
    if (warp == 0) {
        int nw = (blockDim.x + 31) >> 5;
        m = (lane < nw) ? sm[lane] : __uint_as_float(0xFF800000u);
#pragma unroll
        for (int o = 16; o >= 1; o >>= 1) m = fmaxf(m, __shfl_xor_sync(0xffffffffu, m, o));
        if (lane == 0) atomicMaxFloat(&g_max, m);
    }
}

// ---------------- kernel: node-centric aggregate + skip + bias + ELU -----
// One warp per node. Lane l handles output cols l*4..l*4+3 (head = l>>3).
__global__ __launch_bounds__(256) void k_node(const float* __restrict__ x,
                                              const float* __restrict__ bias,
                                              float* __restrict__ out) {
    int n = (blockIdx.x * blockDim.x + threadIdx.x) >> 5;
    if (n >= N_NODES) return;
    const int lane = threadIdx.x & 31;
    const int head = lane >> 3;
    const int start = g_off[n];
    const int deg = g_cnt[n];
    const float gm = g_max;
    float4 st4 = *(const float4*)&g_s_trg[n * NH];

    // pass 1: per-head softmax denominator (lane-parallel over edges)
    float d0 = 0.f, d1 = 0.f, d2 = 0.f, d3 = 0.f;
    for (int k = lane; k < deg; k += 32) {
        int src = g_esrc[start + k];
        float4 ss = *(const float4*)&g_s_src[src * NH];
        float v;
        v = ss.x + st4.x; v = v > 0.f ? v : LEAKY * v; d0 += expf(v - gm);
        v = ss.y + st4.y; v = v > 0.f ? v : LEAKY * v; d1 += expf(v - gm);
        v = ss.z + st4.z; v = v > 0.f ? v : LEAKY * v; d2 += expf(v - gm);
        v = ss.w + st4.w; v = v > 0.f ? v : LEAKY * v; d3 += expf(v - gm);
    }
#pragma unroll
    for (int o = 16; o >= 1; o >>= 1) {
        d0 += __shfl_xor_sync(0xffffffffu, d0, o);
        d1 += __shfl_xor_sync(0xffffffffu, d1, o);
        d2 += __shfl_xor_sync(0xffffffffu, d2, o);
        d3 += __shfl_xor_sync(0xffffffffu, d3, o);
    }
    float denom = (head == 0) ? d0 : (head == 1) ? d1 : (head == 2) ? d2 : d3;
    const float rdenom = 1.f / (denom + 1e-16f);
    const float st_h = (head == 0) ? st4.x : (head == 1) ? st4.y : (head == 2) ? st4.z : st4.w;

    // pass 2: gather proj[src] weighted by attention, accumulate
    float4 acc = make_float4(0.f, 0.f, 0.f, 0.f);
    if (deg > 0) {
        int src = g_esrc[start];
        for (int k = 0; k < deg; k++) {
            int nsrc = (k + 1 < deg) ? g_esrc[start + k + 1] : 0;   // prefetch
            float s = g_s_src[src * NH + head];
            float v = s + st_h; v = v > 0.f ? v : LEAKY * v;
            float att = expf(v - gm) * rdenom;
            float4 p = *(const float4*)&g_proj[src * FIN + lane * 4];
            acc.x = fmaf(p.x, att, acc.x);
            acc.y = fmaf(p.y, att, acc.y);
            acc.z = fmaf(p.z, att, acc.z);
            acc.w = fmaf(p.w, att, acc.w);
            src = nsrc;
        }
    }

    // epilogue: skip + bias + ELU
    float4 xb = *(const float4*)&x[n * FIN + lane * 4];
    float4 bb = *(const float4*)&bias[lane * 4];
    float4 r;
    r.x = acc.x + xb.x + bb.x; r.x = r.x > 0.f ? r.x : expm1f(r.x);
    r.y = acc.y + xb.y + bb.y; r.y = r.y > 0.f ? r.y : expm1f(r.y);
    r.z = acc.z + xb.z + bb.z; r.z = r.z > 0.f ? r.z : expm1f(r.z);
    r.w = acc.w + xb.w + bb.w; r.w = r.w > 0.f ? r.w : expm1f(r.w);
    *(float4*)&out[n * FIN + lane * 4] = r;
}

// ---------------- launch -------------------------------------------------
extern "C" void kernel_launch(void* const* d_in, const int* in_sizes, int n_in,
                              void* d_out, int out_size) {
    const float* x     = (const float*)d_in[0];
    const int*   ei    = (const int*)d_in[1];   // JAX x64 disabled: int32
    const float* W     = (const float*)d_in[2];
    const float* a_src = (const float*)d_in[3];
    const float* a_trg = (const float*)d_in[4];
    const float* bias  = (const float*)d_in[5];
    float* out = (float*)d_out;

    const int E = in_sizes[1] / 2;

    k_zero<<<NB_CHUNKS, 256>>>();
    k_gemm<<<(N_NODES + BM - 1) / BM, 256>>>(x, W, a_src, a_trg);
    k_count<<<(E + 255) / 256, 256>>>(ei, E);
    k_scan1<<<NB_CHUNKS, 256>>>();
    k_scan2<<<1, 256>>>(NB_CHUNKS);
    k_scan_add<<<NB_CHUNKS, 256>>>();
    k_scatter<<<(E + 255) / 256, 256>>>(ei, E);
    k_edge_max<<<1024, 256>>>(ei, E);
    k_node<<<(N_NODES * 32 + 255) / 256, 256>>>(x, bias, out);
}